// round 6
// baseline (speedup 1.0000x reference)
#include <cuda_runtime.h>
#include <cuda_fp16.h>
#include <mma.h>
#include <math.h>
#include <stdint.h>

using namespace nvcuda;

// ---------------- problem constants ----------------
#define HID    768
#define BATCH  4
#define SSYN   4096
#define SSEM   2048
#define SEMROWS 8192     // BATCH*SSEM
#define SYNROWS 16384    // BATCH*SSYN

// ---------------- scratch (device globals; no allocations allowed) --------
__device__ __half g_semh[SEMROWS*HID];
__device__ __half g_synh[SYNROWS*HID];
__device__ __half g_wt[6*HID*HID];        // transposed weights [out,in] -> [N,K]
__device__ __half g_q1[SEMROWS*HID];
__device__ __half g_k1[SYNROWS*HID];
__device__ __half g_q2[SYNROWS*HID];
__device__ __half g_k2[SEMROWS*HID];
__device__ __half g_v1t[HID*SYNROWS];     // V1^T [768, 16384]
__device__ __half g_v2t[HID*SEMROWS];     // V2^T [768, 8192]
__device__ float  g_s1[(long long)BATCH*SSEM*SSYN];   // fp32 scores
__device__ float  g_s2[(long long)BATCH*SSYN*SSEM];
__device__ __half g_p1[(long long)BATCH*SSEM*SSYN];   // fp16 probs
__device__ __half g_p2[(long long)BATCH*SSYN*SSEM];

struct H4 { __half2 a, b; };   // 8-byte packed 4x half

// ------- fp16 wmma GEMM, 128x256x64 CTA tile, 64x64 warp tile, 3-stage ----
// C[z] = (A[z] @ B[z]^T (+bias)) * scale
// A row-major [M,K] (lda=K), B row-major [N,K] (row stride ldb), C row-major ldc=N.
// M%128==0, N%256==0, K%64==0.
constexpr int TM = 128, TN = 256, TK = 64;
constexpr int KP = 72;                         // padded halfs per tile row (144B)
constexpr int A_H = TM * KP;                   // 9216 halfs
constexpr int B_H = TN * KP;                   // 18432 halfs
constexpr int STAGE_H = A_H + B_H;             // 27648 halfs
constexpr int NSTAGE = 3;
constexpr int SMEM_GEMM = NSTAGE * STAGE_H * 2 + 1024;   // 166912 B

__device__ __forceinline__ void cpa16(__half* dst, const __half* src) {
    unsigned d = (unsigned)__cvta_generic_to_shared(dst);
    asm volatile("cp.async.cg.shared.global [%0], [%1], 16;" :: "r"(d), "l"(src));
}

// BIASMODE: 0=none, 1=bias over columns (n), 2=bias over rows (m)
template<int BIASMODE, typename CT>
__global__ __launch_bounds__(256, 1)
void gemm_fp16(const __half* __restrict__ A, const __half* __restrict__ B,
               const float* __restrict__ bias, CT* __restrict__ C,
               int N, int K, int ldb,
               long long sA, long long sB, long long sC, float scale)
{
    extern __shared__ __align__(16) __half sm[];
    float* biassm = (float*)((char*)sm + NSTAGE * STAGE_H * 2);

    const int tid = threadIdx.x;
    const int wid = tid >> 5;
    const int wm  = wid & 1;               // warp row 0..1 (64 rows)
    const int wn  = wid >> 1;              // warp col 0..3 (64 cols)

    const long long z = blockIdx.z;
    const int n0 = blockIdx.x * TN;
    const long long row0 = (long long)blockIdx.y * TM;
    const __half* Ab = A + z * sA + row0 * K;
    const __half* Bb = B + z * sB + (long long)n0 * ldb;
    CT*           Cb = C + z * sC;

    if (BIASMODE == 1) biassm[tid] = bias[n0 + tid];             // TN=256
    if (BIASMODE == 2 && tid < TM) biassm[tid] = bias[row0 + tid];

    wmma::fragment<wmma::matrix_a, 16, 16, 16, __half, wmma::row_major> af[4];
    wmma::fragment<wmma::matrix_b, 16, 16, 16, __half, wmma::col_major> bf[4];
    wmma::fragment<wmma::accumulator, 16, 16, 16, float> cf[4][4];
    #pragma unroll
    for (int i = 0; i < 4; i++)
        #pragma unroll
        for (int j = 0; j < 4; j++)
            wmma::fill_fragment(cf[i][j], 0.0f);

    const int nt = K / TK;

    auto load_tiles = [&](int t, int stage) {
        const __half* Ag = Ab + (long long)t * TK;
        __half* da = sm + stage * STAGE_H;
        #pragma unroll
        for (int i = 0; i < 4; i++) {                 // A: 128x64 = 1024 chunks
            int idx = tid + (i << 8);
            int r = idx >> 3, c = (idx & 7) << 3;     // 8 halfs = 16B
            cpa16(da + r * KP + c, Ag + (long long)r * K + c);
        }
        const __half* Bg = Bb + (long long)t * TK;
        __half* db = da + A_H;
        #pragma unroll
        for (int i = 0; i < 8; i++) {                 // B: 256x64 = 2048 chunks
            int idx = tid + (i << 8);
            int r = idx >> 3, c = (idx & 7) << 3;
            cpa16(db + r * KP + c, Bg + (long long)r * ldb + c);
        }
    };

    load_tiles(0, 0);
    asm volatile("cp.async.commit_group;");
    if (nt > 1) load_tiles(1, 1);
    asm volatile("cp.async.commit_group;");

    for (int t = 0; t < nt; t++) {
        if (t == nt - 1)
            asm volatile("cp.async.wait_group 0;");
        else
            asm volatile("cp.async.wait_group 1;");
        __syncthreads();

        if (t + 2 < nt) load_tiles(t + 2, (t + 2) % NSTAGE);
        asm volatile("cp.async.commit_group;");

        const __half* Ad = sm + (t % NSTAGE) * STAGE_H;
        const __half* Bd = Ad + A_H;
        #pragma unroll
        for (int kk = 0; kk < 4; kk++) {
            #pragma unroll
            for (int i = 0; i < 4; i++)
                wmma::load_matrix_sync(af[i], Ad + (wm * 64 + i * 16) * KP + kk * 16, KP);
            #pragma unroll
            for (int j = 0; j < 4; j++)
                wmma::load_matrix_sync(bf[j], Bd + (wn * 64 + j * 16) * KP + kk * 16, KP);
            #pragma unroll
            for (int i = 0; i < 4; i++)
                #pragma unroll
                for (int j = 0; j < 4; j++)
                    wmma::mma_sync(cf[i][j], af[i], bf[j], cf[i][j]);
        }
    }
    __syncthreads();

    // ---- epilogue: stage fp32 accumulators through smem, fused bias+scale ----
    float* Cs = (float*)sm;    // [128][260] = 133120 B (fits in stage region)
    #pragma unroll
    for (int i = 0; i < 4; i++)
        #pragma unroll
        for (int j = 0; j < 4; j++)
            wmma::store_matrix_sync(Cs + (wm * 64 + i * 16) * 260 + wn * 64 + j * 16,
                                    cf[i][j], 260, wmma::mem_row_major);
    __syncthreads();

    if (sizeof(CT) == 4) {
        // fp32 output: 128x256 floats, 32 float4 per thread
        #pragma unroll
        for (int i = 0; i < 32; i++) {
            int idx = tid + (i << 8);
            int r = idx >> 6, c = (idx & 63) << 2;
            float4 v = *reinterpret_cast<const float4*>(Cs + r * 260 + c);
            if (BIASMODE == 1) {
                v.x += biassm[c + 0]; v.y += biassm[c + 1];
                v.z += biassm[c + 2]; v.w += biassm[c + 3];
            }
            if (BIASMODE == 2) {
                float rb = biassm[r];
                v.x += rb; v.y += rb; v.z += rb; v.w += rb;
            }
            v.x *= scale; v.y *= scale; v.z *= scale; v.w *= scale;
            *reinterpret_cast<float4*>((float*)Cb + (row0 + r) * N + n0 + c) = v;
        }
    } else {
        // fp16 output: 16 chunks of 8 halfs
        #pragma unroll
        for (int i = 0; i < 16; i++) {
            int idx = tid + (i << 8);
            int r = idx >> 5, c = (idx & 31) << 3;
            float4 v0 = *reinterpret_cast<const float4*>(Cs + r * 260 + c);
            float4 v1 = *reinterpret_cast<const float4*>(Cs + r * 260 + c + 4);
            if (BIASMODE == 1) {
                v0.x += biassm[c + 0]; v0.y += biassm[c + 1];
                v0.z += biassm[c + 2]; v0.w += biassm[c + 3];
                v1.x += biassm[c + 4]; v1.y += biassm[c + 5];
                v1.z += biassm[c + 6]; v1.w += biassm[c + 7];
            }
            if (BIASMODE == 2) {
                float rb = biassm[r];
                v0.x += rb; v0.y += rb; v0.z += rb; v0.w += rb;
                v1.x += rb; v1.y += rb; v1.z += rb; v1.w += rb;
            }
            v0.x *= scale; v0.y *= scale; v0.z *= scale; v0.w *= scale;
            v1.x *= scale; v1.y *= scale; v1.z *= scale; v1.w *= scale;
            __half2 h0 = __floats2half2_rn(v0.x, v0.y);
            __half2 h1 = __floats2half2_rn(v0.z, v0.w);
            __half2 h2 = __floats2half2_rn(v1.x, v1.y);
            __half2 h3 = __floats2half2_rn(v1.z, v1.w);
            uint4 pk;
            pk.x = *(unsigned*)&h0; pk.y = *(unsigned*)&h1;
            pk.z = *(unsigned*)&h2; pk.w = *(unsigned*)&h3;
            *reinterpret_cast<uint4*>((__half*)Cb + (row0 + r) * N + n0 + c) = pk;
        }
    }
}

// ---------------- elementwise fp32 -> fp16 ----------------
__global__ __launch_bounds__(256)
void cvt_half(const float* __restrict__ in, __half* __restrict__ out, int n)
{
    int i = (blockIdx.x * 256 + threadIdx.x) * 4;
    if (i < n) {
        float4 v = *reinterpret_cast<const float4*>(in + i);
        H4 h; __half2* hp = (__half2*)&h;
        hp[0] = __floats2half2_rn(v.x, v.y);
        hp[1] = __floats2half2_rn(v.z, v.w);
        *reinterpret_cast<H4*>(out + i) = h;
    }
}

// ---------------- transpose fp32 -> fp16 (weights) ----------------
__global__ __launch_bounds__(256)
void transpose_h(const float* __restrict__ in, __half* __restrict__ out, int R, int C)
{
    __shared__ float ts[32][33];
    int tx = threadIdx.x & 31, ty = threadIdx.x >> 5;
    int c0 = blockIdx.x * 32, r0 = blockIdx.y * 32;
    #pragma unroll
    for (int j = 0; j < 4; j++)
        ts[ty + j * 8][tx] = in[(long long)(r0 + ty + j * 8) * C + c0 + tx];
    __syncthreads();
    #pragma unroll
    for (int j = 0; j < 4; j++)
        out[(long long)(c0 + ty + j * 8) * R + r0 + tx] = __float2half_rn(ts[tx][ty + j * 8]);
}

// ---------------- row softmax: fp32 scores in, fp16 probs out -------------
template<int NV>
__global__ __launch_bounds__(256)
void softmax_rows(const float* __restrict__ S, __half* __restrict__ P, int ncols)
{
    __shared__ float red[8];
    const float* p = S + (long long)blockIdx.x * ncols;
    __half* q = P + (long long)blockIdx.x * ncols;
    const int tid = threadIdx.x;

    float4 v[NV];
    float m = -3.4e38f;
    #pragma unroll
    for (int i = 0; i < NV; i++) {
        v[i] = reinterpret_cast<const float4*>(p)[tid + (i << 8)];
        m = fmaxf(m, fmaxf(fmaxf(v[i].x, v[i].y), fmaxf(v[i].z, v[i].w)));
    }
    #pragma unroll
    for (int o = 16; o > 0; o >>= 1) m = fmaxf(m, __shfl_xor_sync(0xffffffffu, m, o));
    if ((tid & 31) == 0) red[tid >> 5] = m;
    __syncthreads();
    m = red[0];
    #pragma unroll
    for (int w = 1; w < 8; w++) m = fmaxf(m, red[w]);
    __syncthreads();

    float s = 0.0f;
    #pragma unroll
    for (int i = 0; i < NV; i++) {
        v[i].x = __expf(v[i].x - m); s += v[i].x;
        v[i].y = __expf(v[i].y - m); s += v[i].y;
        v[i].z = __expf(v[i].z - m); s += v[i].z;
        v[i].w = __expf(v[i].w - m); s += v[i].w;
    }
    #pragma unroll
    for (int o = 16; o > 0; o >>= 1) s += __shfl_xor_sync(0xffffffffu, s, o);
    if ((tid & 31) == 0) red[tid >> 5] = s;
    __syncthreads();
    s = red[0];
    #pragma unroll
    for (int w = 1; w < 8; w++) s += red[w];

    const float inv = 1.0f / s;
    #pragma unroll
    for (int i = 0; i < NV; i++) {
        H4 h; __half2* hp = (__half2*)&h;
        hp[0] = __floats2half2_rn(v[i].x * inv, v[i].y * inv);
        hp[1] = __floats2half2_rn(v[i].z * inv, v[i].w * inv);
        reinterpret_cast<H4*>(q)[tid + (i << 8)] = h;
    }
}

// ---------------- launcher ----------------
extern "C" void kernel_launch(void* const* d_in, const int* in_sizes, int n_in,
                              void* d_out, int out_size)
{
    const float* syn = (const float*)d_in[0];   // [4, 4096, 768]
    const float* sem = (const float*)d_in[1];   // [4, 2048, 768]
    const float* Wq1 = (const float*)d_in[2];  const float* bq1 = (const float*)d_in[3];
    const float* Wk1 = (const float*)d_in[4];  const float* bk1 = (const float*)d_in[5];
    const float* Wv1 = (const float*)d_in[6];  const float* bv1 = (const float*)d_in[7];
    const float* Wq2 = (const float*)d_in[8];  const float* bq2 = (const float*)d_in[9];
    const float* Wk2 = (const float*)d_in[10]; const float* bk2 = (const float*)d_in[11];
    const float* Wv2 = (const float*)d_in[12]; const float* bv2 = (const float*)d_in[13];

    float* o1 = (float*)d_out;                      // enhanced_semantic [4,2048,768]
    float* o2 = o1 + (long long)SEMROWS * HID;      // enhanced_syntax   [4,4096,768]

    __half *semh, *synh, *wt, *q1, *k1, *q2, *k2, *v1t, *v2t, *p1, *p2;
    float *s1, *s2;
    cudaGetSymbolAddress((void**)&semh, g_semh);
    cudaGetSymbolAddress((void**)&synh, g_synh);
    cudaGetSymbolAddress((void**)&wt, g_wt);
    cudaGetSymbolAddress((void**)&q1, g_q1);
    cudaGetSymbolAddress((void**)&k1, g_k1);
    cudaGetSymbolAddress((void**)&q2, g_q2);
    cudaGetSymbolAddress((void**)&k2, g_k2);
    cudaGetSymbolAddress((void**)&v1t, g_v1t);
    cudaGetSymbolAddress((void**)&v2t, g_v2t);
    cudaGetSymbolAddress((void**)&s1, g_s1);
    cudaGetSymbolAddress((void**)&s2, g_s2);
    cudaGetSymbolAddress((void**)&p1, g_p1);
    cudaGetSymbolAddress((void**)&p2, g_p2);

    cudaFuncSetAttribute(gemm_fp16<1, __half>,
                         cudaFuncAttributeMaxDynamicSharedMemorySize, SMEM_GEMM);
    cudaFuncSetAttribute(gemm_fp16<2, __half>,
                         cudaFuncAttributeMaxDynamicSharedMemorySize, SMEM_GEMM);
    cudaFuncSetAttribute(gemm_fp16<0, float>,
                         cudaFuncAttributeMaxDynamicSharedMemorySize, SMEM_GEMM);

    const float scale = 1.0f / sqrtf((float)HID);
    const long long WN = (long long)HID * HID;

    // ---- convert inputs; transpose+convert weights ([in,out] -> [out,in]) ----
    cvt_half<<<SEMROWS * HID / 1024, 256>>>(sem, semh, SEMROWS * HID);
    cvt_half<<<SYNROWS * HID / 1024, 256>>>(syn, synh, SYNROWS * HID);
    dim3 tg(HID / 32, HID / 32);
    transpose_h<<<tg, 256>>>(Wq1, wt + 0 * WN, HID, HID);
    transpose_h<<<tg, 256>>>(Wk1, wt + 1 * WN, HID, HID);
    transpose_h<<<tg, 256>>>(Wv1, wt + 2 * WN, HID, HID);
    transpose_h<<<tg, 256>>>(Wq2, wt + 3 * WN, HID, HID);
    transpose_h<<<tg, 256>>>(Wk2, wt + 4 * WN, HID, HID);
    transpose_h<<<tg, 256>>>(Wv2, wt + 5 * WN, HID, HID);

    // ---- Q/K projections: C[m,h] = X[m,k] Wt[h,k] + b[h] ----
    gemm_fp16<1, __half><<<dim3(HID/TN, SEMROWS/TM, 1), 256, SMEM_GEMM>>>(
        semh, wt + 0 * WN, bq1, q1, HID, HID, HID, 0, 0, 0, 1.0f);
    gemm_fp16<1, __half><<<dim3(HID/TN, SYNROWS/TM, 1), 256, SMEM_GEMM>>>(
        synh, wt + 1 * WN, bk1, k1, HID, HID, HID, 0, 0, 0, 1.0f);
    gemm_fp16<1, __half><<<dim3(HID/TN, SYNROWS/TM, 1), 256, SMEM_GEMM>>>(
        synh, wt + 3 * WN, bq2, q2, HID, HID, HID, 0, 0, 0, 1.0f);
    gemm_fp16<1, __half><<<dim3(HID/TN, SEMROWS/TM, 1), 256, SMEM_GEMM>>>(
        semh, wt + 4 * WN, bk2, k2, HID, HID, HID, 0, 0, 0, 1.0f);

    // ---- V projections, produced TRANSPOSED: Vt[h,s] = Wt_v[h,k] X[s,k] + b[h] ----
    gemm_fp16<2, __half><<<dim3(SYNROWS/TN, HID/TM, 1), 256, SMEM_GEMM>>>(
        wt + 2 * WN, synh, bv1, v1t, SYNROWS, HID, HID, 0, 0, 0, 1.0f);
    gemm_fp16<2, __half><<<dim3(SEMROWS/TN, HID/TM, 1), 256, SMEM_GEMM>>>(
        wt + 5 * WN, semh, bv2, v2t, SEMROWS, HID, HID, 0, 0, 0, 1.0f);

    // ---- scores (fp32 out): S[q,k] = Q[q,h] K[k,h] * scale, batched z=4 ----
    gemm_fp16<0, float><<<dim3(SSYN/TN, SSEM/TM, BATCH), 256, SMEM_GEMM>>>(
        q1, k1, nullptr, s1, SSYN, HID, HID,
        (long long)SSEM*HID, (long long)SSYN*HID, (long long)SSEM*SSYN, scale);
    gemm_fp16<0, float><<<dim3(SSEM/TN, SSYN/TM, BATCH), 256, SMEM_GEMM>>>(
        q2, k2, nullptr, s2, SSEM, HID, HID,
        (long long)SSYN*HID, (long long)SSEM*HID, (long long)SSYN*SSEM, scale);

    // ---- softmax over keys: fp32 in, fp16 probs out ----
    softmax_rows<4><<<SEMROWS, 256>>>(s1, p1, SSYN);
    softmax_rows<2><<<SYNROWS, 256>>>(s2, p2, SSEM);

    // ---- output: O[q,h] = P[q,s] Vt[h,s], batched z=4 (Vt batch-sliced on K) ----
    gemm_fp16<0, float><<<dim3(HID/TN, SSEM/TM, BATCH), 256, SMEM_GEMM>>>(
        p1, v1t, nullptr, o1, HID, SSYN, SYNROWS,
        (long long)SSEM*SSYN, (long long)SSYN, (long long)SSEM*HID, 1.0f);
    gemm_fp16<0, float><<<dim3(HID/TN, SSYN/TM, BATCH), 256, SMEM_GEMM>>>(
        p2, v2t, nullptr, o2, HID, SSEM, SEMROWS,
        (long long)SSYN*SSEM, (long long)SSEM, (long long)SSYN*HID, 1.0f);
}

// round 7
// speedup vs baseline: 1.1905x; 1.1905x over previous
#include <cuda_runtime.h>
#include <cuda_fp16.h>
#include <mma.h>
#include <math.h>
#include <stdint.h>

using namespace nvcuda;

// ---------------- problem constants ----------------
#define HID    768
#define BATCH  4
#define SSYN   4096
#define SSEM   2048
#define SEMROWS 8192     // BATCH*SSEM
#define SYNROWS 16384    // BATCH*SSYN

// ---------------- scratch (device globals; no allocations allowed) --------
__device__ __half g_semh[SEMROWS*HID];
__device__ __half g_synh[SYNROWS*HID];
__device__ __half g_wt[6*HID*HID];        // transposed weights [out,in] -> [N,K]
__device__ __half g_q1[SEMROWS*HID];
__device__ __half g_k1[SYNROWS*HID];
__device__ __half g_q2[SYNROWS*HID];
__device__ __half g_k2[SEMROWS*HID];
__device__ __half g_v1t[HID*SYNROWS];     // V1^T [768, 16384]
__device__ __half g_v2t[HID*SEMROWS];     // V2^T [768, 8192]
__device__ float  g_s1[(long long)BATCH*SSEM*SSYN];   // fp32 scores
__device__ float  g_s2[(long long)BATCH*SSYN*SSEM];
__device__ __half g_p1[(long long)BATCH*SSEM*SSYN];   // fp16 probs
__device__ __half g_p2[(long long)BATCH*SSYN*SSEM];

struct H4 { __half2 a, b; };   // 8-byte packed 4x half

// ---------------- fp16 wmma GEMM, 128x128x64 tile, cp.async double buffer --
// C = (A @ B^T (+bias)) * scale
// A row-major [M,K] (lda=K), B row-major [N,K] (row stride ldb), C row-major ldc=N.
// DUAL: blockIdx.z in {0,1} selects (B,bias,C) vs (B2,bias2,C2), same A.
// !DUAL: blockIdx.z is the batch index with strides sA/sB/sC.
constexpr int TM = 128, TN = 128, TK = 64;
constexpr int KP = 72;                        // padded halfs per tile row (144B)
constexpr int TILE_H = 128 * KP;              // 9216 halfs per operand
constexpr int STAGE_H = 2 * TILE_H;           // A+B per stage
constexpr int STAGE_BYTES = STAGE_H * 2;      // 36864
constexpr int SMEM_GEMM = 2 * STAGE_BYTES + 512;  // 74240 B

__device__ __forceinline__ void cpa16(__half* dst, const __half* src) {
    unsigned d = (unsigned)__cvta_generic_to_shared(dst);
    asm volatile("cp.async.cg.shared.global [%0], [%1], 16;" :: "r"(d), "l"(src));
}

// BIASMODE: 0=none, 1=bias over columns (n), 2=bias over rows (m)
template<int BIASMODE, typename CT, bool DUAL>
__global__ __launch_bounds__(256, 2)
void gemm_fp16(const __half* __restrict__ A,
               const __half* __restrict__ B,  const __half* __restrict__ B2,
               const float* __restrict__ bias, const float* __restrict__ bias2,
               CT* __restrict__ C, CT* __restrict__ C2,
               int N, int K, int ldb,
               long long sA, long long sB, long long sC, float scale)
{
    extern __shared__ __align__(16) __half sm[];
    float* biassm = (float*)((char*)sm + 2 * STAGE_BYTES);

    const int tid = threadIdx.x;
    const int wid = tid >> 5;
    const int wm  = wid & 1;               // warp row 0..1 (64 rows)
    const int wn  = wid >> 1;              // warp col 0..3 (32 cols)

    const __half* Bsel = B;
    const float*  bsel = bias;
    CT*           Csel = C;
    long long z = 0;
    if (DUAL) {
        if (blockIdx.z == 1) { Bsel = B2; bsel = bias2; Csel = C2; }
    } else {
        z = blockIdx.z;
    }

    const int n0 = blockIdx.x * TN;
    const long long row0 = (long long)blockIdx.y * TM;
    const __half* Ab = A + z * sA + row0 * K;
    const __half* Bb = Bsel + z * sB + (long long)n0 * ldb;
    CT*           Cb = Csel + z * sC;

    if (BIASMODE == 1 && tid < TN) biassm[tid] = bsel[n0 + tid];
    if (BIASMODE == 2 && tid < TM) biassm[tid] = bsel[row0 + tid];

    wmma::fragment<wmma::matrix_a, 16, 16, 16, __half, wmma::row_major> af[4];
    wmma::fragment<wmma::matrix_b, 16, 16, 16, __half, wmma::col_major> bf[2];
    wmma::fragment<wmma::accumulator, 16, 16, 16, float> cf[4][2];
    #pragma unroll
    for (int i = 0; i < 4; i++)
        #pragma unroll
        for (int j = 0; j < 2; j++)
            wmma::fill_fragment(cf[i][j], 0.0f);

    const int nt = K / TK;

    auto load_tiles = [&](int t, int stage) {
        const __half* Ag = Ab + (long long)t * TK;
        __half* da = sm + stage * STAGE_H;
        #pragma unroll
        for (int i = 0; i < 4; i++) {
            int idx = tid + (i << 8);
            int r = idx >> 3, c = (idx & 7) << 3;     // 8 halfs = 16B
            cpa16(da + r * KP + c, Ag + (long long)r * K + c);
        }
        const __half* Bg = Bb + (long long)t * TK;
        __half* db = da + TILE_H;
        #pragma unroll
        for (int i = 0; i < 4; i++) {
            int idx = tid + (i << 8);
            int r = idx >> 3, c = (idx & 7) << 3;
            cpa16(db + r * KP + c, Bg + (long long)r * ldb + c);
        }
    };

    load_tiles(0, 0);
    asm volatile("cp.async.commit_group;");

    for (int t = 0; t < nt; t++) {
        if (t + 1 < nt) load_tiles(t + 1, (t + 1) & 1);
        asm volatile("cp.async.commit_group;");
        if (t + 1 < nt)
            asm volatile("cp.async.wait_group 1;");
        else
            asm volatile("cp.async.wait_group 0;");
        __syncthreads();

        const __half* Ad = sm + (t & 1) * STAGE_H;
        const __half* Bd = Ad + TILE_H;
        #pragma unroll
        for (int kk = 0; kk < 4; kk++) {
            #pragma unroll
            for (int i = 0; i < 4; i++)
                wmma::load_matrix_sync(af[i], Ad + (wm * 64 + i * 16) * KP + kk * 16, KP);
            #pragma unroll
            for (int j = 0; j < 2; j++)
                wmma::load_matrix_sync(bf[j], Bd + (wn * 32 + j * 16) * KP + kk * 16, KP);
            #pragma unroll
            for (int i = 0; i < 4; i++)
                #pragma unroll
                for (int j = 0; j < 2; j++)
                    wmma::mma_sync(cf[i][j], af[i], bf[j], cf[i][j]);
        }
        __syncthreads();
    }

    // ---- epilogue: stage fp32 accumulators through smem, fused bias+scale ----
    float* Cs = (float*)sm;    // [128][136] = 69632 B (fits in stage region)
    #pragma unroll
    for (int i = 0; i < 4; i++)
        #pragma unroll
        for (int j = 0; j < 2; j++)
            wmma::store_matrix_sync(Cs + (wm * 64 + i * 16) * 136 + wn * 32 + j * 16,
                                    cf[i][j], 136, wmma::mem_row_major);
    __syncthreads();

    if (sizeof(CT) == 4) {
        // fp32 output
        #pragma unroll
        for (int i = 0; i < 16; i++) {
            int idx = tid + (i << 8);
            int r = idx >> 5, c = (idx & 31) << 2;
            float4 v = *reinterpret_cast<const float4*>(Cs + r * 136 + c);
            if (BIASMODE == 1) {
                v.x += biassm[c + 0]; v.y += biassm[c + 1];
                v.z += biassm[c + 2]; v.w += biassm[c + 3];
            }
            if (BIASMODE == 2) {
                float rb = biassm[r];
                v.x += rb; v.y += rb; v.z += rb; v.w += rb;
            }
            v.x *= scale; v.y *= scale; v.z *= scale; v.w *= scale;
            *reinterpret_cast<float4*>((float*)Cb + (row0 + r) * N + n0 + c) = v;
        }
    } else {
        // fp16 output, 8 halfs per chunk
        #pragma unroll
        for (int i = 0; i < 8; i++) {
            int idx = tid + (i << 8);
            int r = idx >> 4, c = (idx & 15) << 3;
            float4 v0 = *reinterpret_cast<const float4*>(Cs + r * 136 + c);
            float4 v1 = *reinterpret_cast<const float4*>(Cs + r * 136 + c + 4);
            if (BIASMODE == 1) {
                v0.x += biassm[c + 0]; v0.y += biassm[c + 1];
                v0.z += biassm[c + 2]; v0.w += biassm[c + 3];
                v1.x += biassm[c + 4]; v1.y += biassm[c + 5];
                v1.z += biassm[c + 6]; v1.w += biassm[c + 7];
            }
            if (BIASMODE == 2) {
                float rb = biassm[r];
                v0.x += rb; v0.y += rb; v0.z += rb; v0.w += rb;
                v1.x += rb; v1.y += rb; v1.z += rb; v1.w += rb;
            }
            v0.x *= scale; v0.y *= scale; v0.z *= scale; v0.w *= scale;
            v1.x *= scale; v1.y *= scale; v1.z *= scale; v1.w *= scale;
            __half2 h0 = __floats2half2_rn(v0.x, v0.y);
            __half2 h1 = __floats2half2_rn(v0.z, v0.w);
            __half2 h2 = __floats2half2_rn(v1.x, v1.y);
            __half2 h3 = __floats2half2_rn(v1.z, v1.w);
            uint4 pk;
            pk.x = *(unsigned*)&h0; pk.y = *(unsigned*)&h1;
            pk.z = *(unsigned*)&h2; pk.w = *(unsigned*)&h3;
            *reinterpret_cast<uint4*>((__half*)Cb + (row0 + r) * N + n0 + c) = pk;
        }
    }
}

// ---------------- elementwise fp32 -> fp16 ----------------
__global__ __launch_bounds__(256)
void cvt_half(const float* __restrict__ in, __half* __restrict__ out, int n)
{
    int i = (blockIdx.x * 256 + threadIdx.x) * 4;
    if (i < n) {
        float4 v = *reinterpret_cast<const float4*>(in + i);
        H4 h; __half2* hp = (__half2*)&h;
        hp[0] = __floats2half2_rn(v.x, v.y);
        hp[1] = __floats2half2_rn(v.z, v.w);
        *reinterpret_cast<H4*>(out + i) = h;
    }
}

// -------- batched transpose fp32 -> fp16 (all 6 weights in one launch) ----
struct WSet { const float* in[6]; };
__global__ __launch_bounds__(256)
void transpose_h6(WSet ws, __half* __restrict__ out)
{
    __shared__ float ts[32][33];
    const int R = HID, C = HID;
    const float* in = ws.in[blockIdx.z];
    __half* o = out + (long long)blockIdx.z * HID * HID;
    int tx = threadIdx.x & 31, ty = threadIdx.x >> 5;
    int c0 = blockIdx.x * 32, r0 = blockIdx.y * 32;
    #pragma unroll
    for (int j = 0; j < 4; j++)
        ts[ty + j * 8][tx] = in[(long long)(r0 + ty + j * 8) * C + c0 + tx];
    __syncthreads();
    #pragma unroll
    for (int j = 0; j < 4; j++)
        o[(long long)(c0 + ty + j * 8) * R + r0 + tx] = __float2half_rn(ts[tx][ty + j * 8]);
}

// ---------------- row softmax: fp32 scores in, fp16 probs out -------------
template<int NV>
__global__ __launch_bounds__(256)
void softmax_rows(const float* __restrict__ S, __half* __restrict__ P, int ncols)
{
    __shared__ float red[8];
    const float* p = S + (long long)blockIdx.x * ncols;
    __half* q = P + (long long)blockIdx.x * ncols;
    const int tid = threadIdx.x;

    float4 v[NV];
    float m = -3.4e38f;
    #pragma unroll
    for (int i = 0; i < NV; i++) {
        v[i] = reinterpret_cast<const float4*>(p)[tid + (i << 8)];
        m = fmaxf(m, fmaxf(fmaxf(v[i].x, v[i].y), fmaxf(v[i].z, v[i].w)));
    }
    #pragma unroll
    for (int o = 16; o > 0; o >>= 1) m = fmaxf(m, __shfl_xor_sync(0xffffffffu, m, o));
    if ((tid & 31) == 0) red[tid >> 5] = m;
    __syncthreads();
    m = red[0];
    #pragma unroll
    for (int w = 1; w < 8; w++) m = fmaxf(m, red[w]);
    __syncthreads();

    float s = 0.0f;
    #pragma unroll
    for (int i = 0; i < NV; i++) {
        v[i].x = __expf(v[i].x - m); s += v[i].x;
        v[i].y = __expf(v[i].y - m); s += v[i].y;
        v[i].z = __expf(v[i].z - m); s += v[i].z;
        v[i].w = __expf(v[i].w - m); s += v[i].w;
    }
    #pragma unroll
    for (int o = 16; o > 0; o >>= 1) s += __shfl_xor_sync(0xffffffffu, s, o);
    if ((tid & 31) == 0) red[tid >> 5] = s;
    __syncthreads();
    s = red[0];
    #pragma unroll
    for (int w = 1; w < 8; w++) s += red[w];

    const float inv = 1.0f / s;
    #pragma unroll
    for (int i = 0; i < NV; i++) {
        H4 h; __half2* hp = (__half2*)&h;
        hp[0] = __floats2half2_rn(v[i].x * inv, v[i].y * inv);
        hp[1] = __floats2half2_rn(v[i].z * inv, v[i].w * inv);
        reinterpret_cast<H4*>(q)[tid + (i << 8)] = h;
    }
}

// ---------------- launcher ----------------
extern "C" void kernel_launch(void* const* d_in, const int* in_sizes, int n_in,
                              void* d_out, int out_size)
{
    const float* syn = (const float*)d_in[0];   // [4, 4096, 768]
    const float* sem = (const float*)d_in[1];   // [4, 2048, 768]
    const float* Wq1 = (const float*)d_in[2];  const float* bq1 = (const float*)d_in[3];
    const float* Wk1 = (const float*)d_in[4];  const float* bk1 = (const float*)d_in[5];
    const float* Wv1 = (const float*)d_in[6];  const float* bv1 = (const float*)d_in[7];
    const float* Wq2 = (const float*)d_in[8];  const float* bq2 = (const float*)d_in[9];
    const float* Wk2 = (const float*)d_in[10]; const float* bk2 = (const float*)d_in[11];
    const float* Wv2 = (const float*)d_in[12]; const float* bv2 = (const float*)d_in[13];

    float* o1 = (float*)d_out;                      // enhanced_semantic [4,2048,768]
    float* o2 = o1 + (long long)SEMROWS * HID;      // enhanced_syntax   [4,4096,768]

    __half *semh, *synh, *wt, *q1, *k1, *q2, *k2, *v1t, *v2t, *p1, *p2;
    float *s1, *s2;
    cudaGetSymbolAddress((void**)&semh, g_semh);
    cudaGetSymbolAddress((void**)&synh, g_synh);
    cudaGetSymbolAddress((void**)&wt, g_wt);
    cudaGetSymbolAddress((void**)&q1, g_q1);
    cudaGetSymbolAddress((void**)&k1, g_k1);
    cudaGetSymbolAddress((void**)&q2, g_q2);
    cudaGetSymbolAddress((void**)&k2, g_k2);
    cudaGetSymbolAddress((void**)&v1t, g_v1t);
    cudaGetSymbolAddress((void**)&v2t, g_v2t);
    cudaGetSymbolAddress((void**)&s1, g_s1);
    cudaGetSymbolAddress((void**)&s2, g_s2);
    cudaGetSymbolAddress((void**)&p1, g_p1);
    cudaGetSymbolAddress((void**)&p2, g_p2);

    cudaFuncSetAttribute(gemm_fp16<1, __half, true>,
                         cudaFuncAttributeMaxDynamicSharedMemorySize, SMEM_GEMM);
    cudaFuncSetAttribute(gemm_fp16<2, __half, false>,
                         cudaFuncAttributeMaxDynamicSharedMemorySize, SMEM_GEMM);
    cudaFuncSetAttribute(gemm_fp16<0, float, false>,
                         cudaFuncAttributeMaxDynamicSharedMemorySize, SMEM_GEMM);

    const float scale = 1.0f / sqrtf((float)HID);
    const long long WN = (long long)HID * HID;

    // ---- convert inputs; transpose+convert all weights in one launch ----
    cvt_half<<<SEMROWS * HID / 1024, 256>>>(sem, semh, SEMROWS * HID);
    cvt_half<<<SYNROWS * HID / 1024, 256>>>(syn, synh, SYNROWS * HID);
    WSet ws;
    ws.in[0] = Wq1; ws.in[1] = Wk1; ws.in[2] = Wv1;
    ws.in[3] = Wq2; ws.in[4] = Wk2; ws.in[5] = Wv2;
    transpose_h6<<<dim3(HID / 32, HID / 32, 6), 256>>>(ws, wt);

    // ---- Q/K projections, dual-output (shared A, z selects weight/out) ----
    // sem -> {q1 (Wq1,bq1), k2 (Wk2,bk2)}
    gemm_fp16<1, __half, true><<<dim3(HID/TN, SEMROWS/TM, 2), 256, SMEM_GEMM>>>(
        semh, wt + 0 * WN, wt + 4 * WN, bq1, bk2, q1, k2,
        HID, HID, HID, 0, 0, 0, 1.0f);
    // syn -> {k1 (Wk1,bk1), q2 (Wq2,bq2)}
    gemm_fp16<1, __half, true><<<dim3(HID/TN, SYNROWS/TM, 2), 256, SMEM_GEMM>>>(
        synh, wt + 1 * WN, wt + 3 * WN, bk1, bq2, k1, q2,
        HID, HID, HID, 0, 0, 0, 1.0f);

    // ---- V projections, produced TRANSPOSED: Vt[h,s] = Wt_v[h,k] X[s,k] + b[h] ----
    gemm_fp16<2, __half, false><<<dim3(SYNROWS/TN, HID/TM, 1), 256, SMEM_GEMM>>>(
        wt + 2 * WN, synh, nullptr, bv1, nullptr, v1t, nullptr,
        SYNROWS, HID, HID, 0, 0, 0, 1.0f);
    gemm_fp16<2, __half, false><<<dim3(SEMROWS/TN, HID/TM, 1), 256, SMEM_GEMM>>>(
        wt + 5 * WN, semh, nullptr, bv2, nullptr, v2t, nullptr,
        SEMROWS, HID, HID, 0, 0, 0, 1.0f);

    // ---- scores (fp32 out): S[q,k] = Q[q,h] K[k,h] * scale, batched z=4 ----
    gemm_fp16<0, float, false><<<dim3(SSYN/TN, SSEM/TM, BATCH), 256, SMEM_GEMM>>>(
        q1, k1, nullptr, nullptr, nullptr, s1, nullptr,
        SSYN, HID, HID,
        (long long)SSEM*HID, (long long)SSYN*HID, (long long)SSEM*SSYN, scale);
    gemm_fp16<0, float, false><<<dim3(SSEM/TN, SSYN/TM, BATCH), 256, SMEM_GEMM>>>(
        q2, k2, nullptr, nullptr, nullptr, s2, nullptr,
        SSEM, HID, HID,
        (long long)SSYN*HID, (long long)SSEM*HID, (long long)SSYN*SSEM, scale);

    // ---- softmax over keys: fp32 in, fp16 probs out ----
    softmax_rows<4><<<SEMROWS, 256>>>(s1, p1, SSYN);
    softmax_rows<2><<<SYNROWS, 256>>>(s2, p2, SSEM);

    // ---- output: O[q,h] = P[q,s] Vt[h,s], batched z=4 (Vt batch-sliced on K) ----
    gemm_fp16<0, float, false><<<dim3(HID/TN, SSEM/TM, BATCH), 256, SMEM_GEMM>>>(
        p1, v1t, nullptr, nullptr, nullptr, o1, nullptr,
        HID, SSYN, SYNROWS,
        (long long)SSEM*SSYN, (long long)SSYN, (long long)SSEM*HID, 1.0f);
    gemm_fp16<0, float, false><<<dim3(HID/TN, SSYN/TM, BATCH), 256, SMEM_GEMM>>>(
        p2, v2t, nullptr, nullptr, nullptr, o2, nullptr,
        HID, SSEM, SEMROWS,
        (long long)SSYN*SSEM, (long long)SSEM, (long long)SSYN*HID, 1.0f);
}